// round 1
// baseline (speedup 1.0000x reference)
#include <cuda_runtime.h>
#include <cuda_bf16.h>
#include <math_constants.h>
#include <cstdint>

// Problem constants
#define N_BOXES   262144
#define STRIDE    85
#define N_CLASSES 80
#define CONF_THRES 0.8f
#define NMS_THRES  0.4f
#define MAX_DET    300
#define CAP        2048      // per-class bucket capacity (mean 655, sigma 26 -> +54 sigma)
#define MAXKEEP    4096      // global keep-list capacity

// ---------------- device scratch (static, no allocations) ----------------
__device__ int   g_cnt[N_CLASSES];
__device__ float g_x1[N_CLASSES * CAP];
__device__ float g_y1[N_CLASSES * CAP];
__device__ float g_x2[N_CLASSES * CAP];
__device__ float g_y2[N_CLASSES * CAP];
__device__ float g_sc[N_CLASSES * CAP];   // score = obj * class_conf
__device__ float g_cf[N_CLASSES * CAP];   // class_conf

__device__ int   g_keep_n;
__device__ float g_keep_score[MAXKEEP];
__device__ float g_keep_conf [MAXKEEP];
__device__ int   g_keep_cls  [MAXKEEP];

// ---------------- kernel 0: reset counters ----------------
__global__ void k_init() {
    int t = threadIdx.x;
    if (t < N_CLASSES) g_cnt[t] = 0;
    if (t == 0) g_keep_n = 0;
}

// ---------------- kernel 1: score / filter / bucket (warp per box) ----------------
__global__ void k_score(const float* __restrict__ det) {
    int gw   = (blockIdx.x * blockDim.x + threadIdx.x) >> 5;
    int lane = threadIdx.x & 31;
    if (gw >= N_BOXES) return;

    const float* p = det + (long long)gw * STRIDE;
    float a = p[lane];            // pos 0..31
    float b = p[lane + 32];       // pos 32..63
    float c = (lane + 64 < STRIDE) ? p[lane + 64] : -1e30f;  // pos 64..84

    // argmax over class scores (positions 5..84), ties -> smallest class index
    float bv = -1e30f; int bi = 0;
    if (lane >= 5)            { bv = a; bi = lane - 5; }
    { if (b > bv)             { bv = b; bi = lane + 27; } }          // pos lane+32 -> cls lane+27
    if (lane + 64 < STRIDE)   { if (c > bv) { bv = c; bi = lane + 59; } }

    #pragma unroll
    for (int off = 16; off; off >>= 1) {
        float ov = __shfl_down_sync(0xffffffffu, bv, off);
        int   oi = __shfl_down_sync(0xffffffffu, bi, off);
        if (ov > bv || (ov == bv && oi < bi)) { bv = ov; bi = oi; }
    }

    float obj = __shfl_sync(0xffffffffu, a, 4);
    float x   = __shfl_sync(0xffffffffu, a, 0);
    float y   = __shfl_sync(0xffffffffu, a, 1);
    float w   = __shfl_sync(0xffffffffu, a, 2);
    float h   = __shfl_sync(0xffffffffu, a, 3);

    if (lane == 0 && obj >= CONF_THRES) {
        float conf  = bv;
        float score = __fmul_rn(obj, conf);
        float hw = __fmul_rn(w, 0.5f);
        float hh = __fmul_rn(h, 0.5f);
        float x1 = __fsub_rn(x, hw), y1 = __fsub_rn(y, hh);
        float x2 = __fadd_rn(x, hw), y2 = __fadd_rn(y, hh);
        int slot = atomicAdd(&g_cnt[bi], 1);
        if (slot < CAP) {
            int o = bi * CAP + slot;
            g_x1[o] = x1; g_y1[o] = y1; g_x2[o] = x2; g_y2[o] = y2;
            g_sc[o] = score; g_cf[o] = conf;
        }
    }
}

// ---------------- kernel 2: per-class greedy NMS (one block per class) ----------------
__global__ __launch_bounds__(512) void k_nms() {
    __shared__ float skey[CAP];
    __shared__ short sid [CAP];
    __shared__ float sx1[CAP], sy1[CAP], sx2[CAP], sy2[CAP];
    __shared__ int   s_next;

    int c = blockIdx.x;
    int n = g_cnt[c];
    if (n > CAP) n = CAP;
    if (n == 0) return;

    int m = 1; while (m < n) m <<= 1;    // power-of-2 pad for bitonic
    int base = c * CAP;
    int tid = threadIdx.x, nt = blockDim.x;

    for (int i = tid; i < m; i += nt) {
        if (i < n) { skey[i] = g_sc[base + i]; sid[i] = (short)i; }
        else       { skey[i] = -CUDART_INF_F; sid[i] = (short)i; }
    }
    __syncthreads();

    // bitonic sort descending by (score, idx)
    for (int k = 2; k <= m; k <<= 1) {
        for (int j = k >> 1; j > 0; j >>= 1) {
            for (int i = tid; i < m; i += nt) {
                int l = i ^ j;
                if (l > i) {
                    float ka = skey[i], kb = skey[l];
                    short ia = sid[i],  ib = sid[l];
                    bool aLess   = (ka < kb) || (ka == kb && ia < ib);
                    bool dirDesc = ((i & k) == 0);
                    if (aLess == dirDesc) {
                        skey[i] = kb; skey[l] = ka;
                        sid[i]  = ib; sid[l]  = ia;
                    }
                }
            }
            __syncthreads();
        }
    }

    // gather coords in sorted order
    for (int i = tid; i < n; i += nt) {
        int o = base + sid[i];
        sx1[i] = g_x1[o]; sy1[i] = g_y1[o]; sx2[i] = g_x2[o]; sy2[i] = g_y2[o];
    }
    __syncthreads();

    int cur = 0;   // index 0 holds the max score -> first pick
    while (cur < n) {
        if (tid == 0) {
            int kk = atomicAdd(&g_keep_n, 1);
            if (kk < MAXKEEP) {
                g_keep_score[kk] = skey[cur];
                g_keep_conf [kk] = g_cf[base + sid[cur]];
                g_keep_cls  [kk] = c;
            }
            s_next = 0x7fffffff;
        }
        __syncthreads();

        float px1 = sx1[cur], py1 = sy1[cur], px2 = sx2[cur], py2 = sy2[cur];
        float pa  = __fmul_rn(__fadd_rn(__fsub_rn(px2, px1), 1.0f),
                              __fadd_rn(__fsub_rn(py2, py1), 1.0f));

        for (int j = cur + 1 + tid; j < n; j += nt) {
            if (skey[j] != -CUDART_INF_F) {
                float bx1 = sx1[j], by1 = sy1[j], bx2 = sx2[j], by2 = sy2[j];
                float xx1 = fmaxf(px1, bx1), yy1 = fmaxf(py1, by1);
                float xx2 = fminf(px2, bx2), yy2 = fminf(py2, by2);
                float iw  = fmaxf(__fadd_rn(__fsub_rn(xx2, xx1), 1.0f), 0.0f);
                float ih  = fmaxf(__fadd_rn(__fsub_rn(yy2, yy1), 1.0f), 0.0f);
                float inter = __fmul_rn(iw, ih);
                float a2  = __fmul_rn(__fadd_rn(__fsub_rn(bx2, bx1), 1.0f),
                                      __fadd_rn(__fsub_rn(by2, by1), 1.0f));
                float den = __fadd_rn(__fsub_rn(__fadd_rn(pa, a2), inter), 1e-16f);
                float iou = __fdiv_rn(inter, den);
                if (iou > NMS_THRES) skey[j] = -CUDART_INF_F;
                else                 atomicMin(&s_next, j);   // next pick = min surviving idx
            }
        }
        __syncthreads();
        cur = s_next;
        __syncthreads();
    }
}

// ---------------- kernel 3: global top-300 by score, then sort by conf, emit ----------------
__global__ __launch_bounds__(512) void k_final(float* __restrict__ out, int out_size) {
    __shared__ float kkey[MAXKEEP];
    __shared__ int   kid [MAXKEEP];
    __shared__ float ckey[512];
    __shared__ float ccls[512];

    int tid = threadIdx.x, nt = blockDim.x;
    int K = g_keep_n; if (K > MAXKEEP) K = MAXKEEP;

    int m = 2; while (m < K) m <<= 1;
    for (int i = tid; i < m; i += nt) {
        if (i < K) { kkey[i] = g_keep_score[i]; kid[i] = i; }
        else       { kkey[i] = -CUDART_INF_F;   kid[i] = i; }
    }
    __syncthreads();

    // bitonic descending by (score, idx)
    for (int k = 2; k <= m; k <<= 1) {
        for (int j = k >> 1; j > 0; j >>= 1) {
            for (int i = tid; i < m; i += nt) {
                int l = i ^ j;
                if (l > i) {
                    float ka = kkey[i], kb = kkey[l];
                    int   ia = kid[i],  ib = kid[l];
                    bool aLess   = (ka < kb) || (ka == kb && ia < ib);
                    bool dirDesc = ((i & k) == 0);
                    if (aLess == dirDesc) {
                        kkey[i] = kb; kkey[l] = ka;
                        kid[i]  = ib; kid[l]  = ia;
                    }
                }
            }
            __syncthreads();
        }
    }

    int Kc = (K < MAX_DET) ? K : MAX_DET;

    // second sort: top-Kc picks, descending by class_conf
    for (int i = tid; i < 512; i += nt) {
        if (i < Kc) {
            int g = kid[i];
            ckey[i] = g_keep_conf[g];
            ccls[i] = (float)g_keep_cls[g];
        } else {
            ckey[i] = -CUDART_INF_F;
            ccls[i] = 0.0f;
        }
    }
    __syncthreads();

    for (int k = 2; k <= 512; k <<= 1) {
        for (int j = k >> 1; j > 0; j >>= 1) {
            for (int i = tid; i < 512; i += nt) {
                int l = i ^ j;
                if (l > i) {
                    float ka = ckey[i], kb = ckey[l];
                    bool aLess   = (ka < kb);
                    bool dirDesc = ((i & k) == 0);
                    if (aLess == dirDesc) {
                        float pa = ccls[i], pb = ccls[l];
                        ckey[i] = kb; ckey[l] = ka;
                        ccls[i] = pb; ccls[l] = pa;
                    }
                }
            }
            __syncthreads();
        }
    }

    // emit: ids[0..299], probs[300..599]
    for (int i = tid; i < MAX_DET; i += nt) {
        bool v = (i < Kc);
        float idv = v ? ccls[i] : 0.0f;
        float pv  = v ? ckey[i] : 0.0f;
        if (i < out_size)           out[i] = idv;
        if (MAX_DET + i < out_size) out[MAX_DET + i] = pv;
    }
}

// ---------------- launch ----------------
extern "C" void kernel_launch(void* const* d_in, const int* in_sizes, int n_in,
                              void* d_out, int out_size) {
    const float* det = (const float*)d_in[0];
    float* out = (float*)d_out;

    k_init<<<1, 128>>>();

    const int threads = 256;                       // 8 warps -> 8 boxes/block
    const int blocks  = N_BOXES / (threads / 32);  // 32768
    k_score<<<blocks, threads>>>(det);

    k_nms<<<N_CLASSES, 512>>>();

    k_final<<<1, 512>>>(out, out_size);
}

// round 2
// speedup vs baseline: 1.3502x; 1.3502x over previous
#include <cuda_runtime.h>
#include <cuda_bf16.h>
#include <math_constants.h>
#include <cstdint>

#define N_BOXES   262144
#define STRIDE    85
#define N_CLASSES 80
#define CONF_THRES 0.8f
#define NMS_THRES  0.4f
#define MAX_DET    300
#define CAP        1024      // per-class bucket cap (mean 655, sigma ~26 -> +14 sigma)
#define MAXKEEP    2048
#define FULLMASK   0xffffffffu

// ---------------- device scratch ----------------
__device__ int   g_cnt[N_CLASSES];
__device__ float g_x1[N_CLASSES * CAP];
__device__ float g_y1[N_CLASSES * CAP];
__device__ float g_x2[N_CLASSES * CAP];
__device__ float g_y2[N_CLASSES * CAP];
__device__ float g_sc[N_CLASSES * CAP];
__device__ float g_cf[N_CLASSES * CAP];

__device__ int   g_keep_n;
__device__ float g_keep_score[MAXKEEP];
__device__ float g_keep_conf [MAXKEEP];
__device__ int   g_keep_cls  [MAXKEEP];

// comparator: does (ak,ai) come before (bk,bi) in (key desc, id asc) order
__device__ __forceinline__ bool before(float ak, int ai, float bk, int bi) {
    return (ak > bk) || (ak == bk && ai < bi);
}

// ---------------- kernel 0: reset ----------------
__global__ void k_init() {
    int t = threadIdx.x;
    if (t < N_CLASSES) g_cnt[t] = 0;
    if (t == 0) g_keep_n = 0;
}

// ---------------- kernel 1: two-phase filter/score/bucket ----------------
__global__ void k_score(const float* __restrict__ det) {
    int gw   = (blockIdx.x * blockDim.x + threadIdx.x) >> 5;
    int lane = threadIdx.x & 31;
    int base_box = gw << 5;
    if (base_box >= N_BOXES) return;

    // phase 1: each lane probes obj of one box
    float myobj = det[(size_t)(base_box + lane) * STRIDE + 4];
    unsigned mask = __ballot_sync(FULLMASK, myobj >= CONF_THRES);

    // phase 2: warp cooperatively processes each valid box
    while (mask) {
        int b = __ffs(mask) - 1;
        mask &= mask - 1;
        const float* p = det + (size_t)(base_box + b) * STRIDE;

        float a  = p[lane];
        float b2 = p[lane + 32];
        float c2 = (lane < 21) ? p[lane + 64] : -1e30f;

        float bv = -1e30f; int bi = 0;
        if (lane >= 5)          { bv = a;  bi = lane - 5;  }
        if (b2 > bv)            { bv = b2; bi = lane + 27; }
        if (lane < 21 && c2 > bv) { bv = c2; bi = lane + 59; }

        #pragma unroll
        for (int off = 16; off; off >>= 1) {
            float ov = __shfl_down_sync(FULLMASK, bv, off);
            int   oi = __shfl_down_sync(FULLMASK, bi, off);
            if (ov > bv || (ov == bv && oi < bi)) { bv = ov; bi = oi; }
        }

        float x = __shfl_sync(FULLMASK, a, 0);
        float y = __shfl_sync(FULLMASK, a, 1);
        float w = __shfl_sync(FULLMASK, a, 2);
        float h = __shfl_sync(FULLMASK, a, 3);
        float o = __shfl_sync(FULLMASK, a, 4);

        if (lane == 0) {
            float conf  = bv;
            float score = __fmul_rn(o, conf);
            float hw = __fmul_rn(w, 0.5f);
            float hh = __fmul_rn(h, 0.5f);
            int slot = atomicAdd(&g_cnt[bi], 1);
            if (slot < CAP) {
                int idx = bi * CAP + slot;
                g_x1[idx] = __fsub_rn(x, hw);
                g_y1[idx] = __fsub_rn(y, hh);
                g_x2[idx] = __fadd_rn(x, hw);
                g_y2[idx] = __fadd_rn(y, hh);
                g_sc[idx] = score;
                g_cf[idx] = conf;
            }
        }
    }
}

// ---------------- kernel 2: per-class NMS, hybrid bitonic, reg-resident ----------------
__global__ __launch_bounds__(1024) void k_nms() {
    __shared__ float sk[1024];
    __shared__ int   si[1024];
    __shared__ float sx1[1024], sy1[1024], sx2[1024], sy2[1024];
    __shared__ float skey[1024], sconf[1024];
    __shared__ int   s_next;

    int c = blockIdx.x;
    int n = g_cnt[c];
    if (n > CAP) n = CAP;
    if (n == 0) return;

    int t = threadIdx.x;
    int base = c * CAP;

    float key = (t < n) ? g_sc[base + t] : -CUDART_INF_F;
    int   id  = t;

    // hybrid bitonic sort, M = 1024, descending (key, id asc on ties)
    #pragma unroll
    for (int k = 2; k <= 1024; k <<= 1) {
        #pragma unroll
        for (int j = k >> 1; j > 0; j >>= 1) {
            bool dir  = ((t & k) == 0);
            bool iLow = ((t & j) == 0);
            float pk; int pi;
            if (j >= 32) {
                sk[t] = key; si[t] = id;
                __syncthreads();
                pk = sk[t ^ j]; pi = si[t ^ j];
                __syncthreads();
            } else {
                pk = __shfl_xor_sync(FULLMASK, key, j);
                pi = __shfl_xor_sync(FULLMASK, id,  j);
            }
            bool takeMine = (before(key, id, pk, pi) == (iLow == dir));
            if (!takeMine) { key = pk; id = pi; }
        }
    }

    // gather coords/conf in sorted order (thread t owns sorted position t)
    float bx1 = g_x1[base + id], by1 = g_y1[base + id];
    float bx2 = g_x2[base + id], by2 = g_y2[base + id];
    skey[t]  = key;
    sconf[t] = g_cf[base + id];
    sx1[t] = bx1; sy1[t] = by1; sx2[t] = bx2; sy2[t] = by2;
    __syncthreads();

    float a2 = __fmul_rn(__fadd_rn(__fsub_rn(bx2, bx1), 1.0f),
                         __fadd_rn(__fsub_rn(by2, by1), 1.0f));
    bool alive = (t < n);
    int lane = t & 31;

    int cur = 0;
    while (cur < n) {
        if (t == 0) {
            s_next = n;
            int kk = atomicAdd(&g_keep_n, 1);
            if (kk < MAXKEEP) {
                g_keep_score[kk] = skey[cur];
                g_keep_conf [kk] = sconf[cur];
                g_keep_cls  [kk] = c;
            }
        }
        __syncthreads();

        float px1 = sx1[cur], py1 = sy1[cur], px2 = sx2[cur], py2 = sy2[cur];
        float pa  = __fmul_rn(__fadd_rn(__fsub_rn(px2, px1), 1.0f),
                              __fadd_rn(__fsub_rn(py2, py1), 1.0f));

        int cand = n;
        if (alive && t > cur) {
            float xx1 = fmaxf(px1, bx1), yy1 = fmaxf(py1, by1);
            float xx2 = fminf(px2, bx2), yy2 = fminf(py2, by2);
            float iw  = fmaxf(__fadd_rn(__fsub_rn(xx2, xx1), 1.0f), 0.0f);
            float ih  = fmaxf(__fadd_rn(__fsub_rn(yy2, yy1), 1.0f), 0.0f);
            float inter = __fmul_rn(iw, ih);
            float den = __fadd_rn(__fsub_rn(__fadd_rn(pa, a2), inter), 1e-16f);
            float iou = __fdiv_rn(inter, den);
            if (iou > NMS_THRES) alive = false;
            else                 cand = t;
        }
        #pragma unroll
        for (int off = 16; off; off >>= 1)
            cand = min(cand, __shfl_xor_sync(FULLMASK, cand, off));
        if (lane == 0 && cand < n) atomicMin(&s_next, cand);
        __syncthreads();
        cur = s_next;
        __syncthreads();
    }
}

// ---------------- kernel 3: top-300 by score + sort by conf, emit ----------------
__global__ __launch_bounds__(1024) void k_final(float* __restrict__ out, int out_size) {
    __shared__ float sk[2048];
    __shared__ int   si[2048];
    __shared__ float s2k[512];
    __shared__ int   s2c[512];

    int t = threadIdx.x;
    int K = g_keep_n; if (K > MAXKEEP) K = MAXKEEP;

    // two elements per thread: positions t and t+1024
    float k0 = (t        < K) ? g_keep_score[t]        : -CUDART_INF_F;
    float k1 = (t + 1024 < K) ? g_keep_score[t + 1024] : -CUDART_INF_F;
    int   i0 = t, i1 = t + 1024;

    // hybrid bitonic over M=2048 descending
    #pragma unroll
    for (int k = 2; k <= 2048; k <<= 1) {
        #pragma unroll
        for (int j = k >> 1; j > 0; j >>= 1) {
            if (j == 1024) {
                // partner is the thread's own second element; dir at k=2048 is desc
                if (!before(k0, i0, k1, i1)) {
                    float tk = k0; k0 = k1; k1 = tk;
                    int   ti = i0; i0 = i1; i1 = ti;
                }
            } else if (j >= 32) {
                sk[t] = k0; si[t] = i0;
                sk[t + 1024] = k1; si[t + 1024] = i1;
                __syncthreads();
                float p0 = sk[t ^ j];            int q0 = si[t ^ j];
                float p1 = sk[(t ^ j) + 1024];   int q1 = si[(t ^ j) + 1024];
                __syncthreads();
                bool iLow = ((t & j) == 0);
                bool d0 = ((t & k) == 0);
                bool d1 = (((t + 1024) & k) == 0);
                if (before(k0, i0, p0, q0) != (iLow == d0)) { k0 = p0; i0 = q0; }
                if (before(k1, i1, p1, q1) != (iLow == d1)) { k1 = p1; i1 = q1; }
            } else {
                bool iLow = ((t & j) == 0);
                bool d0 = ((t & k) == 0);
                bool d1 = (((t + 1024) & k) == 0);
                float p0 = __shfl_xor_sync(FULLMASK, k0, j);
                int   q0 = __shfl_xor_sync(FULLMASK, i0, j);
                float p1 = __shfl_xor_sync(FULLMASK, k1, j);
                int   q1 = __shfl_xor_sync(FULLMASK, i1, j);
                if (before(k0, i0, p0, q0) != (iLow == d0)) { k0 = p0; i0 = q0; }
                if (before(k1, i1, p1, q1) != (iLow == d1)) { k1 = p1; i1 = q1; }
            }
        }
    }

    int Kc = (K < MAX_DET) ? K : MAX_DET;

    // second sort: top-Kc picks by conf desc (512-wide, first 512 threads active)
    float ck = -CUDART_INF_F; int cc = 0;
    if (t < 512) {
        if (t < Kc) { ck = g_keep_conf[i0]; cc = g_keep_cls[i0]; }
    }
    #pragma unroll
    for (int k = 2; k <= 512; k <<= 1) {
        #pragma unroll
        for (int j = k >> 1; j > 0; j >>= 1) {
            if (j >= 32) {
                if (t < 512) { s2k[t] = ck; s2c[t] = cc; }
                __syncthreads();
                float pk = 0.0f; int pc = 0;
                if (t < 512) { pk = s2k[t ^ j]; pc = s2c[t ^ j]; }
                __syncthreads();
                if (t < 512) {
                    bool iLow = ((t & j) == 0);
                    bool dir  = ((t & k) == 0);
                    if (before(ck, cc, pk, pc) != (iLow == dir)) { ck = pk; cc = pc; }
                }
            } else {
                if (t < 512) {
                    float pk = __shfl_xor_sync(FULLMASK, ck, j);
                    int   pc = __shfl_xor_sync(FULLMASK, cc, j);
                    bool iLow = ((t & j) == 0);
                    bool dir  = ((t & k) == 0);
                    if (before(ck, cc, pk, pc) != (iLow == dir)) { ck = pk; cc = pc; }
                }
            }
        }
    }

    // emit: ids[0..299], probs[300..599]
    if (t < MAX_DET) {
        bool v = (t < Kc);
        float idv = v ? (float)cc : 0.0f;
        float pv  = v ? ck        : 0.0f;
        if (t < out_size)            out[t] = idv;
        if (MAX_DET + t < out_size)  out[MAX_DET + t] = pv;
    }
}

// ---------------- launch ----------------
extern "C" void kernel_launch(void* const* d_in, const int* in_sizes, int n_in,
                              void* d_out, int out_size) {
    const float* det = (const float*)d_in[0];
    float* out = (float*)d_out;

    k_init<<<1, 128>>>();

    const int threads = 256;                        // 8 warps/block, 32 boxes/warp
    const int blocks  = N_BOXES / threads;          // 1024 blocks
    k_score<<<blocks, threads>>>(det);

    k_nms<<<N_CLASSES, 1024>>>();

    k_final<<<1, 1024>>>(out, out_size);
}